// round 3
// baseline (speedup 1.0000x reference)
#include <cuda_runtime.h>
#include <math.h>

#define Bsz   4
#define Tq    196
#define Lseq  392
#define DM    1024
#define DI    2048
#define DS    16
#define DTR   64
#define MROWS (Bsz*Lseq)   /* 1568 */
#define M2    (Bsz*Tq)     /* 784  */

// ---------------- scratch (static device globals; no allocation) -------------
__device__ float g_temb [Bsz*DM];
__device__ float g_hmlp [Bsz*2048];
__device__ float g_embt [Bsz*DM];
__device__ float g_seq  [MROWS*DM];     // post-LN residual stream
__device__ float g_xnorm[MROWS*DM];     // rms-normed mixer input
__device__ float g_xz   [(size_t)MROWS*2*DI];
__device__ float g_xc   [(size_t)MROWS*DI];   // conv+silu output
__device__ float g_dbc  [MROWS*96];
__device__ float g_delta[(size_t)MROWS*DI];
__device__ float g_y    [(size_t)MROWS*DI];
__device__ float g_yz   [(size_t)M2*DI];
__device__ float g_mo   [(size_t)M2*DM];

// ---------------- K1: timestep embedding -------------------------------------
__global__ void k_temb(const int* __restrict__ ts) {
    int b = blockIdx.x;
    int i = threadIdx.x;                 // 512 threads
    float t = (float)ts[b];
    float freq = expf(-logf(10000.0f) * (float)i / 512.0f);
    float arg = t * freq;
    g_temb[b*DM + i]       = cosf(arg);
    g_temb[b*DM + 512 + i] = sinf(arg);
}

// ---------------- K2/K3: tiny MLP via warp-per-output GEMV -------------------
__global__ void k_mlp(const float* __restrict__ X, const float* __restrict__ W,
                      const float* __restrict__ bias, float* __restrict__ Y,
                      int K, int N, int act) {
    int warp = (blockIdx.x * blockDim.x + threadIdx.x) >> 5;
    int lane = threadIdx.x & 31;
    int b = blockIdx.y;
    if (warp >= N) return;
    const float* x = X + b*K;
    const float* w = W + (size_t)warp*K;
    float s = 0.f;
    for (int k = lane; k < K; k += 32) s = fmaf(x[k], w[k], s);
    #pragma unroll
    for (int o = 16; o; o >>= 1) s += __shfl_xor_sync(0xffffffffu, s, o);
    if (lane == 0) {
        float v = s + bias[warp];
        if (act) v = v / (1.f + expf(-v));
        Y[b*N + warp] = v;
    }
}

// ---------------- K4: build seq (embed + layernorm) and rms-norm input -------
__global__ void k_embed(const float* __restrict__ x_r, const float* __restrict__ motion,
                        const float* __restrict__ pos,
                        const float* __restrict__ ln_g, const float* __restrict__ ln_b,
                        const float* __restrict__ rms_w) {
    int l = blockIdx.x;                  // 0..391
    int b = blockIdx.y;
    int t = threadIdx.x;                 // 256
    __shared__ float r1[8], r2[8];

    float loc[4];
    float s1 = 0.f, s2 = 0.f;
    #pragma unroll
    for (int i = 0; i < 4; i++) {
        int d = t + i*256;
        float v;
        if (l < Tq) {
            v = pos[l*DM + d] + motion[(size_t)(b*Tq + l)*DM + d];
        } else {
            int lr = l - Tq;
            v = pos[lr*DM + d] + x_r[(size_t)(b*Tq + lr)*DM + d] + g_embt[b*DM + d];
        }
        loc[i] = v; s1 += v; s2 += v*v;
    }
    int lane = t & 31, w = t >> 5;
    #pragma unroll
    for (int o = 16; o; o >>= 1) { s1 += __shfl_xor_sync(~0u, s1, o); s2 += __shfl_xor_sync(~0u, s2, o); }
    if (lane == 0) { r1[w] = s1; r2[w] = s2; }
    __syncthreads();
    if (t == 0) {
        float a = 0.f, c = 0.f;
        #pragma unroll
        for (int i = 0; i < 8; i++) { a += r1[i]; c += r2[i]; }
        r1[0] = a; r2[0] = c;
    }
    __syncthreads();
    float mu = r1[0] * (1.f/DM);
    float var = r2[0] * (1.f/DM) - mu*mu;
    float rstd = rsqrtf(var + 1e-5f);
    __syncthreads();

    float q = 0.f;
    size_t row = (size_t)(b*Lseq + l)*DM;
    #pragma unroll
    for (int i = 0; i < 4; i++) {
        int d = t + i*256;
        float ln = (loc[i] - mu) * rstd * ln_g[d] + ln_b[d];
        loc[i] = ln;
        q += ln*ln;
        g_seq[row + d] = ln;
    }
    #pragma unroll
    for (int o = 16; o; o >>= 1) q += __shfl_xor_sync(~0u, q, o);
    if (lane == 0) r1[w] = q;
    __syncthreads();
    if (t == 0) {
        float a = 0.f;
        #pragma unroll
        for (int i = 0; i < 8; i++) a += r1[i];
        r1[0] = a;
    }
    __syncthreads();
    float rrms = rsqrtf(r1[0] * (1.f/DM) + 1e-5f);
    #pragma unroll
    for (int i = 0; i < 4; i++) {
        int d = t + i*256;
        g_xnorm[row + d] = loc[i] * rrms * rms_w[d];
    }
}

// ---------------- SGEMM v2: C[M,N] = A[M,K(lda)] . B[N,K]^T ------------------
// 128x128 tile, BK=16, 256 threads, 8x8 microtile, double-buffered smem.
// EPI==1: softplus(v + bias[n]) epilogue.
#define BM 128
#define BN 128
#define BK 16
#define ASTR (BM+4)
#define BSTR (BN+4)

template<int EPI>
__global__ void __launch_bounds__(256, 2)
sgemm(const float* __restrict__ A, const float* __restrict__ B,
      float* __restrict__ C, int M, int N, int K, int lda,
      const float* __restrict__ bias) {
    __shared__ float As[2][BK][ASTR];
    __shared__ float Bs[2][BK][BSTR];
    int bm0 = blockIdx.y * BM;
    int bn0 = blockIdx.x * BN;
    int tid = threadIdx.x;
    int tx = tid & 15, ty = tid >> 4;

    // load indices: 512 float4 per tile, 2 per thread
    int lr0 = tid >> 2;            // 0..63
    int lc4 = tid & 3;             // 0..3 (k-quad)

    float acc[8][8] = {};
    float4 sa[2], sb[2];           // staging regs

    // ---- preload tile 0 ----
    #pragma unroll
    for (int u = 0; u < 2; u++) {
        int r = lr0 + u*64;
        int gm = bm0 + r, gk = lc4*4;
        float4 v = make_float4(0.f,0.f,0.f,0.f);
        if (gm < M) v = *(const float4*)&A[(size_t)gm*lda + gk];
        As[0][lc4*4+0][r] = v.x; As[0][lc4*4+1][r] = v.y;
        As[0][lc4*4+2][r] = v.z; As[0][lc4*4+3][r] = v.w;
        int gn = bn0 + r;
        float4 w = make_float4(0.f,0.f,0.f,0.f);
        if (gn < N) w = *(const float4*)&B[(size_t)gn*K + gk];
        Bs[0][lc4*4+0][r] = w.x; Bs[0][lc4*4+1][r] = w.y;
        Bs[0][lc4*4+2][r] = w.z; Bs[0][lc4*4+3][r] = w.w;
    }
    __syncthreads();

    int nk = K / BK;
    int buf = 0;
    for (int kt = 0; kt < nk; kt++) {
        // stage next tile from global into regs
        if (kt + 1 < nk) {
            int gk = (kt+1)*BK + lc4*4;
            #pragma unroll
            for (int u = 0; u < 2; u++) {
                int r = lr0 + u*64;
                int gm = bm0 + r;
                sa[u] = make_float4(0.f,0.f,0.f,0.f);
                if (gm < M) sa[u] = *(const float4*)&A[(size_t)gm*lda + gk];
                int gn = bn0 + r;
                sb[u] = make_float4(0.f,0.f,0.f,0.f);
                if (gn < N) sb[u] = *(const float4*)&B[(size_t)gn*K + gk];
            }
        }
        // compute on current buffer
        #pragma unroll
        for (int k = 0; k < BK; k++) {
            float4 a0 = *(const float4*)&As[buf][k][ty*8];
            float4 a1 = *(const float4*)&As[buf][k][ty*8+4];
            float4 b0 = *(const float4*)&Bs[buf][k][tx*8];
            float4 b1 = *(const float4*)&Bs[buf][k][tx*8+4];
            float a[8] = {a0.x,a0.y,a0.z,a0.w,a1.x,a1.y,a1.z,a1.w};
            float bb[8] = {b0.x,b0.y,b0.z,b0.w,b1.x,b1.y,b1.z,b1.w};
            #pragma unroll
            for (int i = 0; i < 8; i++)
                #pragma unroll
                for (int j = 0; j < 8; j++)
                    acc[i][j] = fmaf(a[i], bb[j], acc[i][j]);
        }
        // commit staged tile
        if (kt + 1 < nk) {
            int nb = buf ^ 1;
            #pragma unroll
            for (int u = 0; u < 2; u++) {
                int r = lr0 + u*64;
                As[nb][lc4*4+0][r] = sa[u].x; As[nb][lc4*4+1][r] = sa[u].y;
                As[nb][lc4*4+2][r] = sa[u].z; As[nb][lc4*4+3][r] = sa[u].w;
                Bs[nb][lc4*4+0][r] = sb[u].x; Bs[nb][lc4*4+1][r] = sb[u].y;
                Bs[nb][lc4*4+2][r] = sb[u].z; Bs[nb][lc4*4+3][r] = sb[u].w;
            }
            __syncthreads();
            buf = nb;
        }
    }

    // ---- epilogue ----
    bool full_n = (bn0 + BN <= N);
    #pragma unroll
    for (int i = 0; i < 8; i++) {
        int m = bm0 + ty*8 + i;
        if (m >= M) continue;
        if (EPI == 0 && full_n) {
            #pragma unroll
            for (int jj = 0; jj < 2; jj++) {
                int n = bn0 + tx*8 + jj*4;
                float4 v = make_float4(acc[i][jj*4+0], acc[i][jj*4+1],
                                       acc[i][jj*4+2], acc[i][jj*4+3]);
                *(float4*)&C[(size_t)m*N + n] = v;
            }
        } else {
            #pragma unroll
            for (int j = 0; j < 8; j++) {
                int n = bn0 + tx*8 + j;
                if (n >= N) continue;
                float v = acc[i][j];
                if (EPI == 1) {
                    v += bias[n];
                    v = (v > 20.f) ? v : log1pf(expf(v));
                }
                C[(size_t)m*N + n] = v;
            }
        }
    }
}

// ---------------- K5: depthwise causal conv (w=4) + silu ---------------------
__global__ void k_conv(const float* __restrict__ cw, const float* __restrict__ cb) {
    int idx = blockIdx.x*256 + threadIdx.x;        // over 4*392*2048
    if (idx >= MROWS*DI) return;
    int e = idx & (DI-1);
    int bl = idx >> 11;                            // b*392 + l
    int l = bl % Lseq;
    const float* base = g_xz + (size_t)bl*(2*DI) + e;
    float s = cb[e];
    s = fmaf(base[0], cw[e*4+3], s);
    if (l >= 1) s = fmaf(base[-(2*DI)],   cw[e*4+2], s);
    if (l >= 2) s = fmaf(base[-2*(2*DI)], cw[e*4+1], s);
    if (l >= 3) s = fmaf(base[-3*(2*DI)], cw[e*4+0], s);
    g_xc[idx] = s / (1.f + expf(-s));
}

// ---------------- K6: selective scan (lane-per-state) ------------------------
__global__ void k_scan(const float* __restrict__ A_log) {
    int gtid = blockIdx.x*blockDim.x + threadIdx.x;   // 131072 exact
    int grp = gtid >> 4;                              // (b,e)
    int n = gtid & 15;
    int b = grp >> 11;
    int e = grp & (DI-1);
    float Ac = -expf(A_log[e*DS + n]);
    float h = 0.f;
    const float* dptr = g_delta + (size_t)b*Lseq*DI + e;
    const float* uptr = g_xc    + (size_t)b*Lseq*DI + e;
    const float* bc   = g_dbc   + (size_t)b*Lseq*96;
    float* yptr       = g_y     + (size_t)b*Lseq*DI + e;
    for (int l = 0; l < Lseq; l++) {
        float dv = dptr[(size_t)l*DI];
        float u  = uptr[(size_t)l*DI];
        float Bv = bc[l*96 + 64 + n];
        float Cv = bc[l*96 + 80 + n];
        h = fmaf(__expf(dv*Ac), h, dv*Bv*u);
        float p = h*Cv;
        p += __shfl_xor_sync(0xffffffffu, p, 1);
        p += __shfl_xor_sync(0xffffffffu, p, 2);
        p += __shfl_xor_sync(0xffffffffu, p, 4);
        p += __shfl_xor_sync(0xffffffffu, p, 8);
        if (n == 0) yptr[(size_t)l*DI] = p;
    }
}

// ---------------- K7: gate (only output half of L) ---------------------------
__global__ void k_post(const float* __restrict__ Dp) {
    int idx = blockIdx.x*256 + threadIdx.x;        // over 4*196*2048
    if (idx >= M2*DI) return;
    int e = idx & (DI-1);
    int blr = idx >> 11;                           // b*196 + lr
    int lr = blr % Tq;
    int b  = blr / Tq;
    size_t row = (size_t)(b*Lseq + Tq + lr);
    float y  = g_y [row*DI + e];
    float xc = g_xc[row*DI + e];
    float z  = g_xz[row*(2*DI) + DI + e];
    g_yz[(size_t)blr*DI + e] = (y + xc*Dp[e]) * (z / (1.f + expf(-z)));
}

// ---------------- K8: final residual + layernorm -----------------------------
__global__ void k_final(const float* __restrict__ ln_g, const float* __restrict__ ln_b,
                        float* __restrict__ out) {
    int lr = blockIdx.x;                // 0..195
    int b  = blockIdx.y;
    int t  = threadIdx.x;               // 256
    __shared__ float r1[8], r2[8];
    size_t srow = (size_t)(b*Lseq + Tq + lr)*DM;
    size_t mrow = (size_t)(b*Tq + lr)*DM;

    float loc[4];
    float s1 = 0.f, s2 = 0.f;
    #pragma unroll
    for (int i = 0; i < 4; i++) {
        int d = t + i*256;
        float v = g_seq[srow + d] + g_mo[mrow + d];
        loc[i] = v; s1 += v; s2 += v*v;
    }
    int lane = t & 31, w = t >> 5;
    #pragma unroll
    for (int o = 16; o; o >>= 1) { s1 += __shfl_xor_sync(~0u, s1, o); s2 += __shfl_xor_sync(~0u, s2, o); }
    if (lane == 0) { r1[w] = s1; r2[w] = s2; }
    __syncthreads();
    if (t == 0) {
        float a = 0.f, c = 0.f;
        #pragma unroll
        for (int i = 0; i < 8; i++) { a += r1[i]; c += r2[i]; }
        r1[0] = a; r2[0] = c;
    }
    __syncthreads();
    float mu = r1[0] * (1.f/DM);
    float var = r2[0] * (1.f/DM) - mu*mu;
    float rstd = rsqrtf(var + 1e-5f);
    #pragma unroll
    for (int i = 0; i < 4; i++) {
        int d = t + i*256;
        out[mrow + d] = (loc[i] - mu) * rstd * ln_g[d] + ln_b[d];
    }
}

// ---------------- launch ------------------------------------------------------
extern "C" void kernel_launch(void* const* d_in, const int* in_sizes, int n_in,
                              void* d_out, int out_size) {
    const float* x_r       = (const float*)d_in[0];
    const int*   timesteps = (const int*)  d_in[1];
    const float* motion    = (const float*)d_in[2];
    const float* time_w1   = (const float*)d_in[3];
    const float* time_b1   = (const float*)d_in[4];
    const float* time_w2   = (const float*)d_in[5];
    const float* time_b2   = (const float*)d_in[6];
    const float* pos_emb   = (const float*)d_in[7];
    const float* ln_g      = (const float*)d_in[8];
    const float* ln_b      = (const float*)d_in[9];
    const float* in_proj_w = (const float*)d_in[10];
    const float* conv_w    = (const float*)d_in[11];
    const float* conv_b    = (const float*)d_in[12];
    const float* x_proj_w  = (const float*)d_in[13];
    const float* dt_proj_w = (const float*)d_in[14];
    const float* dt_proj_b = (const float*)d_in[15];
    const float* A_log     = (const float*)d_in[16];
    const float* Dp        = (const float*)d_in[17];
    const float* out_proj_w= (const float*)d_in[18];
    const float* rms_w     = (const float*)d_in[19];
    float* out = (float*)d_out;

    float *p_temb, *p_h, *p_embt, *p_xnorm, *p_xz, *p_xc, *p_dbc, *p_delta, *p_yz, *p_mo;
    cudaGetSymbolAddress((void**)&p_temb,  g_temb);
    cudaGetSymbolAddress((void**)&p_h,     g_hmlp);
    cudaGetSymbolAddress((void**)&p_embt,  g_embt);
    cudaGetSymbolAddress((void**)&p_xnorm, g_xnorm);
    cudaGetSymbolAddress((void**)&p_xz,    g_xz);
    cudaGetSymbolAddress((void**)&p_xc,    g_xc);
    cudaGetSymbolAddress((void**)&p_dbc,   g_dbc);
    cudaGetSymbolAddress((void**)&p_delta, g_delta);
    cudaGetSymbolAddress((void**)&p_yz,    g_yz);
    cudaGetSymbolAddress((void**)&p_mo,    g_mo);

    // time embedding + MLP
    k_temb<<<Bsz, 512>>>(timesteps);
    k_mlp<<<dim3(2048/8, Bsz), 256>>>(p_temb, time_w1, time_b1, p_h, 1024, 2048, 1);
    k_mlp<<<dim3(1024/8, Bsz), 256>>>(p_h, time_w2, time_b2, p_embt, 2048, 1024, 0);

    // embed + LN -> seq, rms -> xnorm
    k_embed<<<dim3(Lseq, Bsz), 256>>>(x_r, motion, pos_emb, ln_g, ln_b, rms_w);

    // in_proj: xz = xnorm @ in_proj_w^T   [1568 x 4096]
    sgemm<0><<<dim3((2*2*DI + BN-1)/BN, (MROWS+BM-1)/BM), 256>>>(p_xnorm, in_proj_w, p_xz,
                                                                 MROWS, 2*DI, DM, DM, nullptr);
    // depthwise conv + silu
    k_conv<<<(MROWS*DI + 255)/256, 256>>>(conv_w, conv_b);

    // x_proj: dbc = xc @ x_proj_w^T   [1568 x 96]
    sgemm<0><<<dim3((96+BN-1)/BN, (MROWS+BM-1)/BM), 256>>>(p_xc, x_proj_w, p_dbc,
                                                           MROWS, 96, DI, DI, nullptr);
    // dt_proj + softplus: delta = softplus(dbc[:, :64] @ dt_proj_w^T + b)  [1568 x 2048]
    sgemm<1><<<dim3(DI/BN, (MROWS+BM-1)/BM), 256>>>(p_dbc, dt_proj_w, p_delta,
                                                    MROWS, DI, DTR, 96, dt_proj_b);
    // selective scan
    k_scan<<<(Bsz*DI*DS)/256, 256>>>(A_log);

    // gating (output half only)
    k_post<<<(M2*DI + 255)/256, 256>>>(Dp);

    // out_proj: mo = yz @ out_proj_w^T  [784 x 1024]
    sgemm<0><<<dim3(DM/BN, (M2+BM-1)/BM), 256>>>(p_yz, out_proj_w, p_mo,
                                                 M2, DM, DI, DI, nullptr);
    // residual + final LN
    k_final<<<dim3(Tq, Bsz), 256>>>(ln_g, ln_b, out);
}

// round 4
// speedup vs baseline: 2.4942x; 2.4942x over previous
#include <cuda_runtime.h>
#include <math.h>
#include <stdint.h>

#define Bsz   4
#define Tq    196
#define Lseq  392
#define DM    1024
#define DI    2048
#define DS    16
#define DTR   64
#define MROWS (Bsz*Lseq)   /* 1568 */
#define M2    (Bsz*Tq)     /* 784  */

// ---------------- scratch (static device globals; no allocation) -------------
__device__ float g_temb [Bsz*DM];
__device__ float g_hmlp [Bsz*2048];
__device__ float g_embt [Bsz*DM];
__device__ float g_seq  [MROWS*DM];
__device__ float g_xnorm[MROWS*DM];
__device__ float g_xz   [(size_t)MROWS*2*DI];
__device__ float g_xc   [(size_t)MROWS*DI];
__device__ float g_dbc  [MROWS*96];
__device__ float g_delta[(size_t)MROWS*DI];
__device__ float g_y    [(size_t)MROWS*DI];
__device__ float g_yz   [(size_t)M2*DI];
__device__ float g_mo   [(size_t)M2*DM];
__device__ float g_part [(size_t)8*MROWS*96 > (size_t)2*M2*DM ? (size_t)8*MROWS*96 : (size_t)2*M2*DM];

// ---------------- helpers -----------------------------------------------------
__device__ __forceinline__ float to_tf32(float x) {
    uint32_t u;
    asm("cvt.rna.tf32.f32 %0, %1;" : "=r"(u) : "f"(x));
    return __uint_as_float(u);
}

__device__ __forceinline__ void mma8(float c[4], const float a[4], const float b[2]) {
    asm volatile(
        "mma.sync.aligned.m16n8k8.row.col.f32.tf32.tf32.f32 "
        "{%0,%1,%2,%3},{%4,%5,%6,%7},{%8,%9},{%0,%1,%2,%3};\n"
        : "+f"(c[0]), "+f"(c[1]), "+f"(c[2]), "+f"(c[3])
        : "r"(__float_as_uint(a[0])), "r"(__float_as_uint(a[1])),
          "r"(__float_as_uint(a[2])), "r"(__float_as_uint(a[3])),
          "r"(__float_as_uint(b[0])), "r"(__float_as_uint(b[1])));
}

#define CP16(dst, src) asm volatile("cp.async.cg.shared.global [%0], [%1], 16;\n" :: "r"(dst), "l"(src))
#define CP_COMMIT()    asm volatile("cp.async.commit_group;\n")
#define CP_WAIT1()     asm volatile("cp.async.wait_group 1;\n")
#define CP_WAIT0()     asm volatile("cp.async.wait_group 0;\n")

// ---------------- K1: timestep embedding -------------------------------------
__global__ void k_temb(const int* __restrict__ ts) {
    int b = blockIdx.x;
    int i = threadIdx.x;
    float t = (float)ts[b];
    float freq = expf(-logf(10000.0f) * (float)i / 512.0f);
    float arg = t * freq;
    g_temb[b*DM + i]       = cosf(arg);
    g_temb[b*DM + 512 + i] = sinf(arg);
}

// ---------------- K2/K3: tiny MLP via warp-per-output GEMV -------------------
__global__ void k_mlp(const float* __restrict__ X, const float* __restrict__ W,
                      const float* __restrict__ bias, float* __restrict__ Y,
                      int K, int N, int act) {
    int warp = (blockIdx.x * blockDim.x + threadIdx.x) >> 5;
    int lane = threadIdx.x & 31;
    int b = blockIdx.y;
    if (warp >= N) return;
    const float* x = X + b*K;
    const float* w = W + (size_t)warp*K;
    float s = 0.f;
    for (int k = lane; k < K; k += 32) s = fmaf(x[k], w[k], s);
    #pragma unroll
    for (int o = 16; o; o >>= 1) s += __shfl_xor_sync(0xffffffffu, s, o);
    if (lane == 0) {
        float v = s + bias[warp];
        if (act) v = v / (1.f + expf(-v));
        Y[b*N + warp] = v;
    }
}

// ---------------- K4: embed + LN -> seq, and RMS-norm -> xnorm ---------------
__global__ void k_embed(const float* __restrict__ x_r, const float* __restrict__ motion,
                        const float* __restrict__ pos,
                        const float* __restrict__ ln_g, const float* __restrict__ ln_b,
                        const float* __restrict__ rms_w) {
    int l = blockIdx.x;
    int b = blockIdx.y;
    int t = threadIdx.x;
    __shared__ float r1[8], r2[8];

    float loc[4];
    float s1 = 0.f, s2 = 0.f;
    #pragma unroll
    for (int i = 0; i < 4; i++) {
        int d = t + i*256;
        float v;
        if (l < Tq) {
            v = pos[l*DM + d] + motion[(size_t)(b*Tq + l)*DM + d];
        } else {
            int lr = l - Tq;
            v = pos[lr*DM + d] + x_r[(size_t)(b*Tq + lr)*DM + d] + g_embt[b*DM + d];
        }
        loc[i] = v; s1 += v; s2 += v*v;
    }
    int lane = t & 31, w = t >> 5;
    #pragma unroll
    for (int o = 16; o; o >>= 1) { s1 += __shfl_xor_sync(~0u, s1, o); s2 += __shfl_xor_sync(~0u, s2, o); }
    if (lane == 0) { r1[w] = s1; r2[w] = s2; }
    __syncthreads();
    if (t == 0) {
        float a = 0.f, c = 0.f;
        #pragma unroll
        for (int i = 0; i < 8; i++) { a += r1[i]; c += r2[i]; }
        r1[0] = a; r2[0] = c;
    }
    __syncthreads();
    float mu = r1[0] * (1.f/DM);
    float var = r2[0] * (1.f/DM) - mu*mu;
    float rstd = rsqrtf(var + 1e-5f);
    __syncthreads();

    float q = 0.f;
    size_t row = (size_t)(b*Lseq + l)*DM;
    #pragma unroll
    for (int i = 0; i < 4; i++) {
        int d = t + i*256;
        float ln = (loc[i] - mu) * rstd * ln_g[d] + ln_b[d];
        loc[i] = ln;
        q += ln*ln;
        g_seq[row + d] = ln;
    }
    #pragma unroll
    for (int o = 16; o; o >>= 1) q += __shfl_xor_sync(~0u, q, o);
    if (lane == 0) r1[w] = q;
    __syncthreads();
    if (t == 0) {
        float a = 0.f;
        #pragma unroll
        for (int i = 0; i < 8; i++) a += r1[i];
        r1[0] = a;
    }
    __syncthreads();
    float rrms = rsqrtf(r1[0] * (1.f/DM) + 1e-5f);
    #pragma unroll
    for (int i = 0; i < 4; i++) {
        int d = t + i*256;
        g_xnorm[row + d] = loc[i] * rrms * rms_w[d];
    }
}

// ---------------- TGEMM: C[M,N] = A[M,K] . B[N,K]^T via tf32 mma (3x split) --
// 128x128 block, 256 threads (8 warps: 2m x 4n, warp tile 64x32).
// Split-K: gridDim.z slices of klen each; slice z writes C + z*M*N.
// EPI==1: softplus(v + bias[n]) epilogue.
template<int EPI>
__global__ void __launch_bounds__(256)
tgemm(const float* __restrict__ A, const float* __restrict__ B,
      float* __restrict__ C, int M, int N, int lda, int ldb,
      int klen, const float* __restrict__ bias) {
    __shared__ float As[2][128][20];
    __shared__ float Bs[2][128][20];
    int tid = threadIdx.x;
    int bm0 = blockIdx.y * 128;
    int bn0 = blockIdx.x * 128;
    int kbeg = blockIdx.z * klen;
    C += (size_t)blockIdx.z * M * N;

    int warp = tid >> 5, lane = tid & 31;
    int wm = (warp & 1) * 64;
    int wn = (warp >> 1) * 32;
    int g = lane >> 2, r = lane & 3;

    float c[4][4][4];
    #pragma unroll
    for (int i = 0; i < 4; i++)
        #pragma unroll
        for (int j = 0; j < 4; j++)
            #pragma unroll
            for (int q = 0; q < 4; q++) c[i][j][q] = 0.f;

    int row_ld = tid >> 2;            // 0..63
    int kc_ld  = (tid & 3) * 4;       // 0,4,8,12

    auto prefetch = [&](int kt, int buf) {
        int k0 = kbeg + kt * 16;
        #pragma unroll
        for (int u = 0; u < 2; u++) {
            int row = row_ld + u * 64;
            int gm = min(bm0 + row, M - 1);
            const float* srca = &A[(size_t)gm * lda + k0 + kc_ld];
            CP16((uint32_t)__cvta_generic_to_shared(&As[buf][row][kc_ld]), srca);
            int gn = min(bn0 + row, N - 1);
            const float* srcb = &B[(size_t)gn * ldb + k0 + kc_ld];
            CP16((uint32_t)__cvta_generic_to_shared(&Bs[buf][row][kc_ld]), srcb);
        }
    };

    int nk = klen / 16;
    prefetch(0, 0);
    CP_COMMIT();

    for (int kt = 0; kt < nk; kt++) {
        int buf = kt & 1;
        if (kt + 1 < nk) {
            prefetch(kt + 1, buf ^ 1);
            CP_COMMIT();
            CP_WAIT1();
        } else {
            CP_WAIT0();
        }
        __syncthreads();

        #pragma unroll
        for (int ks = 0; ks < 2; ks++) {
            int k0 = ks * 8;
            // B fragments (hi/lo)
            float bh[4][2], bl[4][2];
            #pragma unroll
            for (int j = 0; j < 4; j++) {
                float b0 = Bs[buf][wn + j*8 + g][k0 + r];
                float b1 = Bs[buf][wn + j*8 + g][k0 + r + 4];
                bh[j][0] = to_tf32(b0); bl[j][0] = to_tf32(b0 - bh[j][0]);
                bh[j][1] = to_tf32(b1); bl[j][1] = to_tf32(b1 - bh[j][1]);
            }
            #pragma unroll
            for (int i = 0; i < 4; i++) {
                float a0 = As[buf][wm + i*16 + g    ][k0 + r];
                float a1 = As[buf][wm + i*16 + 8 + g][k0 + r];
                float a2 = As[buf][wm + i*16 + g    ][k0 + r + 4];
                float a3 = As[buf][wm + i*16 + 8 + g][k0 + r + 4];
                float ah[4] = {to_tf32(a0), to_tf32(a1), to_tf32(a2), to_tf32(a3)};
                float al[4] = {to_tf32(a0 - ah[0]), to_tf32(a1 - ah[1]),
                               to_tf32(a2 - ah[2]), to_tf32(a3 - ah[3])};
                #pragma unroll
                for (int j = 0; j < 4; j++) {
                    mma8(c[i][j], ah, bh[j]);
                    mma8(c[i][j], al, bh[j]);
                    mma8(c[i][j], ah, bl[j]);
                }
            }
        }
        __syncthreads();
    }

    // epilogue
    #pragma unroll
    for (int i = 0; i < 4; i++) {
        #pragma unroll
        for (int half = 0; half < 2; half++) {
            int m = bm0 + wm + i*16 + g + half*8;
            if (m >= M) continue;
            #pragma unroll
            for (int j = 0; j < 4; j++) {
                int n = bn0 + wn + j*8 + 2*r;
                if (n >= N) continue;
                float v0 = c[i][j][half*2 + 0];
                float v1 = c[i][j][half*2 + 1];
                if (EPI == 1) {
                    v0 += bias[n];
                    v0 = (v0 > 20.f) ? v0 : log1pf(expf(v0));
                    v1 += bias[n + 1];
                    v1 = (v1 > 20.f) ? v1 : log1pf(expf(v1));
                }
                C[(size_t)m*N + n]     = v0;
                C[(size_t)m*N + n + 1] = v1;
            }
        }
    }
}

// ---------------- split-K reduce ---------------------------------------------
__global__ void k_reduce(const float* __restrict__ part, float* __restrict__ out,
                         int MN, int S) {
    int i = blockIdx.x * 256 + threadIdx.x;
    if (i >= MN) return;
    float s = 0.f;
    for (int z = 0; z < S; z++) s += part[(size_t)z*MN + i];
    out[i] = s;
}

// ---------------- K5: depthwise causal conv (w=4) + silu ---------------------
__global__ void k_conv(const float* __restrict__ cw, const float* __restrict__ cb) {
    int idx = blockIdx.x*256 + threadIdx.x;
    if (idx >= MROWS*DI) return;
    int e = idx & (DI-1);
    int bl = idx >> 11;
    int l = bl % Lseq;
    const float* base = g_xz + (size_t)bl*(2*DI) + e;
    float s = cb[e];
    s = fmaf(base[0], cw[e*4+3], s);
    if (l >= 1) s = fmaf(base[-(2*DI)],   cw[e*4+2], s);
    if (l >= 2) s = fmaf(base[-2*(2*DI)], cw[e*4+1], s);
    if (l >= 3) s = fmaf(base[-3*(2*DI)], cw[e*4+0], s);
    g_xc[idx] = s / (1.f + expf(-s));
}

// ---------------- K6: selective scan (lane-per-state) ------------------------
__global__ void k_scan(const float* __restrict__ A_log) {
    int gtid = blockIdx.x*blockDim.x + threadIdx.x;
    int grp = gtid >> 4;
    int n = gtid & 15;
    int b = grp >> 11;
    int e = grp & (DI-1);
    float Ac = -expf(A_log[e*DS + n]);
    float h = 0.f;
    const float* dptr = g_delta + (size_t)b*Lseq*DI + e;
    const float* uptr = g_xc    + (size_t)b*Lseq*DI + e;
    const float* bc   = g_dbc   + (size_t)b*Lseq*96;
    float* yptr       = g_y     + (size_t)b*Lseq*DI + e;
    for (int l = 0; l < Lseq; l++) {
        float dv = dptr[(size_t)l*DI];
        float u  = uptr[(size_t)l*DI];
        float Bv = bc[l*96 + 64 + n];
        float Cv = bc[l*96 + 80 + n];
        h = fmaf(__expf(dv*Ac), h, dv*Bv*u);
        float p = h*Cv;
        p += __shfl_xor_sync(0xffffffffu, p, 1);
        p += __shfl_xor_sync(0xffffffffu, p, 2);
        p += __shfl_xor_sync(0xffffffffu, p, 4);
        p += __shfl_xor_sync(0xffffffffu, p, 8);
        if (n == 0) yptr[(size_t)l*DI] = p;
    }
}

// ---------------- K7: gate (only output half of L) ---------------------------
__global__ void k_post(const float* __restrict__ Dp) {
    int idx = blockIdx.x*256 + threadIdx.x;
    if (idx >= M2*DI) return;
    int e = idx & (DI-1);
    int blr = idx >> 11;
    int lr = blr % Tq;
    int b  = blr / Tq;
    size_t row = (size_t)(b*Lseq + Tq + lr);
    float y  = g_y [row*DI + e];
    float xc = g_xc[row*DI + e];
    float z  = g_xz[row*(2*DI) + DI + e];
    g_yz[(size_t)blr*DI + e] = (y + xc*Dp[e]) * (z / (1.f + expf(-z)));
}

// ---------------- K8: final residual + layernorm -----------------------------
__global__ void k_final(const float* __restrict__ ln_g, const float* __restrict__ ln_b,
                        float* __restrict__ out) {
    int lr = blockIdx.x;
    int b  = blockIdx.y;
    int t  = threadIdx.x;
    __shared__ float r1[8], r2[8];
    size_t srow = (size_t)(b*Lseq + Tq + lr)*DM;
    size_t mrow = (size_t)(b*Tq + lr)*DM;

    float loc[4];
    float s1 = 0.f, s2 = 0.f;
    #pragma unroll
    for (int i = 0; i < 4; i++) {
        int d = t + i*256;
        float v = g_seq[srow + d] + g_mo[mrow + d];
        loc[i] = v; s1 += v; s2 += v*v;
    }
    int lane = t & 31, w = t >> 5;
    #pragma unroll
    for (int o = 16; o; o >>= 1) { s1 += __shfl_xor_sync(~0u, s1, o); s2 += __shfl_xor_sync(~0u, s2, o); }
    if (lane == 0) { r1[w] = s1; r2[w] = s2; }
    __syncthreads();
    if (t == 0) {
        float a = 0.f, c = 0.f;
        #pragma unroll
        for (int i = 0; i < 8; i++) { a += r1[i]; c += r2[i]; }
        r1[0] = a; r2[0] = c;
    }
    __syncthreads();
    float mu = r1[0] * (1.f/DM);
    float var = r2[0] * (1.f/DM) - mu*mu;
    float rstd = rsqrtf(var + 1e-5f);
    #pragma unroll
    for (int i = 0; i < 4; i++) {
        int d = t + i*256;
        out[mrow + d] = (loc[i] - mu) * rstd * ln_g[d] + ln_b[d];
    }
}

// ---------------- launch ------------------------------------------------------
extern "C" void kernel_launch(void* const* d_in, const int* in_sizes, int n_in,
                              void* d_out, int out_size) {
    const float* x_r       = (const float*)d_in[0];
    const int*   timesteps = (const int*)  d_in[1];
    const float* motion    = (const float*)d_in[2];
    const float* time_w1   = (const float*)d_in[3];
    const float* time_b1   = (const float*)d_in[4];
    const float* time_w2   = (const float*)d_in[5];
    const float* time_b2   = (const float*)d_in[6];
    const float* pos_emb   = (const float*)d_in[7];
    const float* ln_g      = (const float*)d_in[8];
    const float* ln_b      = (const float*)d_in[9];
    const float* in_proj_w = (const float*)d_in[10];
    const float* conv_w    = (const float*)d_in[11];
    const float* conv_b    = (const float*)d_in[12];
    const float* x_proj_w  = (const float*)d_in[13];
    const float* dt_proj_w = (const float*)d_in[14];
    const float* dt_proj_b = (const float*)d_in[15];
    const float* A_log     = (const float*)d_in[16];
    const float* Dp        = (const float*)d_in[17];
    const float* out_proj_w= (const float*)d_in[18];
    const float* rms_w     = (const float*)d_in[19];
    float* out = (float*)d_out;

    float *p_temb, *p_h, *p_embt, *p_xnorm, *p_xz, *p_xc, *p_dbc, *p_delta, *p_yz, *p_mo, *p_part;
    cudaGetSymbolAddress((void**)&p_temb,  g_temb);
    cudaGetSymbolAddress((void**)&p_h,     g_hmlp);
    cudaGetSymbolAddress((void**)&p_embt,  g_embt);
    cudaGetSymbolAddress((void**)&p_xnorm, g_xnorm);
    cudaGetSymbolAddress((void**)&p_xz,    g_xz);
    cudaGetSymbolAddress((void**)&p_xc,    g_xc);
    cudaGetSymbolAddress((void**)&p_dbc,   g_dbc);
    cudaGetSymbolAddress((void**)&p_delta, g_delta);
    cudaGetSymbolAddress((void**)&p_yz,    g_yz);
    cudaGetSymbolAddress((void**)&p_mo,    g_mo);
    cudaGetSymbolAddress((void**)&p_part,  g_part);

    // time embedding + MLP
    k_temb<<<Bsz, 512>>>(timesteps);
    k_mlp<<<dim3(2048/8, Bsz), 256>>>(p_temb, time_w1, time_b1, p_h, 1024, 2048, 1);
    k_mlp<<<dim3(1024/8, Bsz), 256>>>(p_h, time_w2, time_b2, p_embt, 2048, 1024, 0);

    // embed + LN -> seq, rms -> xnorm
    k_embed<<<dim3(Lseq, Bsz), 256>>>(x_r, motion, pos_emb, ln_g, ln_b, rms_w);

    // in_proj: xz = xnorm @ in_proj_w^T   [1568 x 4096], K=1024
    tgemm<0><<<dim3(4096/128, (MROWS+127)/128, 1), 256>>>(
        p_xnorm, in_proj_w, p_xz, MROWS, 4096, DM, DM, DM, nullptr);

    // depthwise conv + silu
    k_conv<<<(MROWS*DI + 255)/256, 256>>>(conv_w, conv_b);

    // x_proj: dbc = xc @ x_proj_w^T   [1568 x 96], K=2048, split-K=8
    tgemm<0><<<dim3(1, (MROWS+127)/128, 8), 256>>>(
        p_xc, x_proj_w, p_part, MROWS, 96, DI, DI, DI/8, nullptr);
    k_reduce<<<(MROWS*96 + 255)/256, 256>>>(p_part, p_dbc, MROWS*96, 8);

    // dt_proj + softplus: delta = softplus(dbc[:, :64] @ dt_proj_w^T + b)  [1568 x 2048], K=64
    tgemm<1><<<dim3(DI/128, (MROWS+127)/128, 1), 256>>>(
        p_dbc, dt_proj_w, p_delta, MROWS, DI, 96, DTR, DTR, dt_proj_b);

    // selective scan
    k_scan<<<(Bsz*DI*DS)/256, 256>>>(A_log);

    // gating (output half only)
    k_post<<<(M2*DI + 255)/256, 256>>>(Dp);

    // out_proj: mo = yz @ out_proj_w^T  [784 x 1024], K=2048, split-K=2
    tgemm<0><<<dim3(DM/128, (M2+127)/128, 2), 256>>>(
        p_yz, out_proj_w, p_part, M2, DM, DI, DI, DI/2, nullptr);
    k_reduce<<<(M2*DM + 255)/256, 256>>>(p_part, p_mo, M2*DM, 2);

    // residual + final LN
    k_final<<<dim3(Tq, Bsz), 256>>>(ln_g, ln_b, out);
}

// round 6
// speedup vs baseline: 2.9287x; 1.1742x over previous
#include <cuda_runtime.h>
#include <math.h>
#include <stdint.h>

#define Bsz   4
#define Tq    196
#define Lseq  392
#define DM    1024
#define DI    2048
#define DS    16
#define DTR   64
#define MROWS (Bsz*Lseq)   /* 1568 */
#define M2    (Bsz*Tq)     /* 784  */

// ---------------- scratch (static device globals; no allocation) -------------
__device__ float g_temb [Bsz*DM];
__device__ float g_hmlp [Bsz*2048];
__device__ float g_embt [Bsz*DM];
__device__ float g_seq  [MROWS*DM];
__device__ float g_xnorm[MROWS*DM];
__device__ float g_xz   [(size_t)MROWS*2*DI];
__device__ float g_xc   [(size_t)MROWS*DI];
__device__ float g_dbc  [MROWS*96];
__device__ float g_delta[(size_t)MROWS*DI];
__device__ float g_yz   [(size_t)M2*DI];
__device__ float g_part [(size_t)8*MROWS*96 > (size_t)2*M2*DM ? (size_t)8*MROWS*96 : (size_t)2*M2*DM];

// ---------------- helpers -----------------------------------------------------
__device__ __forceinline__ float to_tf32(float x) {
    uint32_t u;
    asm("cvt.rna.tf32.f32 %0, %1;" : "=r"(u) : "f"(x));
    return __uint_as_float(u);
}

__device__ __forceinline__ void mma8(float c[4], const float a[4], const float b[2]) {
    asm volatile(
        "mma.sync.aligned.m16n8k8.row.col.f32.tf32.tf32.f32 "
        "{%0,%1,%2,%3},{%4,%5,%6,%7},{%8,%9},{%0,%1,%2,%3};\n"
        : "+f"(c[0]), "+f"(c[1]), "+f"(c[2]), "+f"(c[3])
        : "r"(__float_as_uint(a[0])), "r"(__float_as_uint(a[1])),
          "r"(__float_as_uint(a[2])), "r"(__float_as_uint(a[3])),
          "r"(__float_as_uint(b[0])), "r"(__float_as_uint(b[1])));
}

#define CP16(dst, src) asm volatile("cp.async.cg.shared.global [%0], [%1], 16;\n" :: "r"(dst), "l"(src))
#define CP_COMMIT()    asm volatile("cp.async.commit_group;\n")
#define CP_WAIT1()     asm volatile("cp.async.wait_group 1;\n")
#define CP_WAIT0()     asm volatile("cp.async.wait_group 0;\n")

// ---------------- K1: timestep embedding -------------------------------------
__global__ void k_temb(const int* __restrict__ ts) {
    int b = blockIdx.x;
    int i = threadIdx.x;
    float t = (float)ts[b];
    float freq = expf(-logf(10000.0f) * (float)i / 512.0f);
    float arg = t * freq;
    g_temb[b*DM + i]       = cosf(arg);
    g_temb[b*DM + 512 + i] = sinf(arg);
}

// ---------------- K2/K3: tiny MLP via warp-per-output GEMV -------------------
__global__ void k_mlp(const float* __restrict__ X, const float* __restrict__ W,
                      const float* __restrict__ bias, float* __restrict__ Y,
                      int K, int N, int act) {
    int warp = (blockIdx.x * blockDim.x + threadIdx.x) >> 5;
    int lane = threadIdx.x & 31;
    int b = blockIdx.y;
    if (warp >= N) return;
    const float* x = X + b*K;
    const float* w = W + (size_t)warp*K;
    float s = 0.f;
    for (int k = lane; k < K; k += 32) s = fmaf(x[k], w[k], s);
    #pragma unroll
    for (int o = 16; o; o >>= 1) s += __shfl_xor_sync(0xffffffffu, s, o);
    if (lane == 0) {
        float v = s + bias[warp];
        if (act) v = v / (1.f + expf(-v));
        Y[b*N + warp] = v;
    }
}

// ---------------- K4: embed + LN -> seq, and RMS-norm -> xnorm ---------------
__global__ void k_embed(const float* __restrict__ x_r, const float* __restrict__ motion,
                        const float* __restrict__ pos,
                        const float* __restrict__ ln_g, const float* __restrict__ ln_b,
                        const float* __restrict__ rms_w) {
    int l = blockIdx.x;
    int b = blockIdx.y;
    int t = threadIdx.x;
    __shared__ float r1[8], r2[8];

    float loc[4];
    float s1 = 0.f, s2 = 0.f;
    #pragma unroll
    for (int i = 0; i < 4; i++) {
        int d = t + i*256;
        float v;
        if (l < Tq) {
            v = pos[l*DM + d] + motion[(size_t)(b*Tq + l)*DM + d];
        } else {
            int lr = l - Tq;
            v = pos[lr*DM + d] + x_r[(size_t)(b*Tq + lr)*DM + d] + g_embt[b*DM + d];
        }
        loc[i] = v; s1 += v; s2 += v*v;
    }
    int lane = t & 31, w = t >> 5;
    #pragma unroll
    for (int o = 16; o; o >>= 1) { s1 += __shfl_xor_sync(~0u, s1, o); s2 += __shfl_xor_sync(~0u, s2, o); }
    if (lane == 0) { r1[w] = s1; r2[w] = s2; }
    __syncthreads();
    if (t == 0) {
        float a = 0.f, c = 0.f;
        #pragma unroll
        for (int i = 0; i < 8; i++) { a += r1[i]; c += r2[i]; }
        r1[0] = a; r2[0] = c;
    }
    __syncthreads();
    float mu = r1[0] * (1.f/DM);
    float var = r2[0] * (1.f/DM) - mu*mu;
    float rstd = rsqrtf(var + 1e-5f);
    __syncthreads();

    float q = 0.f;
    size_t row = (size_t)(b*Lseq + l)*DM;
    #pragma unroll
    for (int i = 0; i < 4; i++) {
        int d = t + i*256;
        float ln = (loc[i] - mu) * rstd * ln_g[d] + ln_b[d];
        loc[i] = ln;
        q += ln*ln;
        g_seq[row + d] = ln;
    }
    #pragma unroll
    for (int o = 16; o; o >>= 1) q += __shfl_xor_sync(~0u, q, o);
    if (lane == 0) r1[w] = q;
    __syncthreads();
    if (t == 0) {
        float a = 0.f;
        #pragma unroll
        for (int i = 0; i < 8; i++) a += r1[i];
        r1[0] = a;
    }
    __syncthreads();
    float rrms = rsqrtf(r1[0] * (1.f/DM) + 1e-5f);
    #pragma unroll
    for (int i = 0; i < 4; i++) {
        int d = t + i*256;
        g_xnorm[row + d] = loc[i] * rrms * rms_w[d];
    }
}

// ---------------- TGEMM: C[M,N] = A[M,K] . B[N,K]^T via single-pass tf32 -----
// 128x128 block, 256 threads (8 warps: 2m x 4n, warp tile 64x32).
// Split-K: gridDim.z slices of klen each; slice z writes C + z*M*N.
// EPI==1: softplus(v + bias[n]) epilogue.
template<int EPI>
__global__ void __launch_bounds__(256)
tgemm(const float* __restrict__ A, const float* __restrict__ B,
      float* __restrict__ C, int M, int N, int lda, int ldb,
      int klen, const float* __restrict__ bias) {
    __shared__ float As[2][128][20];
    __shared__ float Bs[2][128][20];
    int tid = threadIdx.x;
    int bm0 = blockIdx.y * 128;
    int bn0 = blockIdx.x * 128;
    int kbeg = blockIdx.z * klen;
    C += (size_t)blockIdx.z * M * N;

    int warp = tid >> 5, lane = tid & 31;
    int wm = (warp & 1) * 64;
    int wn = (warp >> 1) * 32;
    int g = lane >> 2, r = lane & 3;

    float c[4][4][4];
    #pragma unroll
    for (int i = 0; i < 4; i++)
        #pragma unroll
        for (int j = 0; j < 4; j++)
            #pragma unroll
            for (int q = 0; q < 4; q++) c[i][j][q] = 0.f;

    int row_ld = tid >> 2;            // 0..63
    int kc_ld  = (tid & 3) * 4;       // 0,4,8,12

    auto prefetch = [&](int kt, int buf) {
        int k0 = kbeg + kt * 16;
        #pragma unroll
        for (int u = 0; u < 2; u++) {
            int row = row_ld + u * 64;
            int gm = min(bm0 + row, M - 1);
            const float* srca = &A[(size_t)gm * lda + k0 + kc_ld];
            CP16((uint32_t)__cvta_generic_to_shared(&As[buf][row][kc_ld]), srca);
            int gn = min(bn0 + row, N - 1);
            const float* srcb = &B[(size_t)gn * ldb + k0 + kc_ld];
            CP16((uint32_t)__cvta_generic_to_shared(&Bs[buf][row][kc_ld]), srcb);
        }
    };

    int nk = klen / 16;
    prefetch(0, 0);
    CP_COMMIT();

    for (int kt = 0; kt < nk; kt++) {
        int buf = kt & 1;
        if (kt + 1 < nk) {
            prefetch(kt + 1, buf ^ 1);
            CP_COMMIT();
            CP_WAIT1();
        } else {
            CP_WAIT0();
        }
        __syncthreads();

        #pragma unroll
        for (int ks = 0; ks < 2; ks++) {
            int k0 = ks * 8;
            float bh[4][2];
            #pragma unroll
            for (int j = 0; j < 4; j++) {
                bh[j][0] = to_tf32(Bs[buf][wn + j*8 + g][k0 + r]);
                bh[j][1] = to_tf32(Bs[buf][wn + j*8 + g][k0 + r + 4]);
            }
            #pragma unroll
            for (int i = 0; i < 4; i++) {
                float ah[4];
                ah[0] = to_tf32(As[buf][wm + i*16 + g    ][k0 + r]);
                ah[1] = to_tf32(As[buf][wm + i*16 + 8 + g][k0 + r]);
                ah[2] = to_tf32(As[buf][wm + i*16 + g    ][k0 + r + 4]);
                ah[3] = to_tf32(As[buf][wm + i*16 + 8 + g][k0 + r + 4]);
                #pragma unroll
                for (int j = 0; j < 4; j++)
                    mma8(c[i][j], ah, bh[j]);
            }
        }
        __syncthreads();
    }

    // epilogue (float2 stores)
    #pragma unroll
    for (int i = 0; i < 4; i++) {
        #pragma unroll
        for (int half = 0; half < 2; half++) {
            int m = bm0 + wm + i*16 + g + half*8;
            if (m >= M) continue;
            #pragma unroll
            for (int j = 0; j < 4; j++) {
                int n = bn0 + wn + j*8 + 2*r;
                if (n >= N) continue;
                float v0 = c[i][j][half*2 + 0];
                float v1 = c[i][j][half*2 + 1];
                if (EPI == 1) {
                    v0 += bias[n];
                    v0 = (v0 > 20.f) ? v0 : log1pf(expf(v0));
                    v1 += bias[n + 1];
                    v1 = (v1 > 20.f) ? v1 : log1pf(expf(v1));
                }
                *(float2*)&C[(size_t)m*N + n] = make_float2(v0, v1);
            }
        }
    }
}

// ---------------- split-K reduce (x_proj only) --------------------------------
__global__ void k_reduce(const float* __restrict__ part, float* __restrict__ out,
                         int MN, int S) {
    int i = blockIdx.x * 256 + threadIdx.x;
    if (i >= MN) return;
    float s = 0.f;
    for (int z = 0; z < S; z++) s += part[(size_t)z*MN + i];
    out[i] = s;
}

// ---------------- K5: depthwise causal conv (w=4) + silu ---------------------
__global__ void k_conv(const float* __restrict__ cw, const float* __restrict__ cb) {
    int idx = blockIdx.x*256 + threadIdx.x;
    if (idx >= MROWS*DI) return;
    int e = idx & (DI-1);
    int bl = idx >> 11;
    int l = bl % Lseq;
    const float* base = g_xz + (size_t)bl*(2*DI) + e;
    float s = cb[e];
    s = fmaf(base[0], cw[e*4+3], s);
    if (l >= 1) s = fmaf(base[-(2*DI)],   cw[e*4+2], s);
    if (l >= 2) s = fmaf(base[-2*(2*DI)], cw[e*4+1], s);
    if (l >= 3) s = fmaf(base[-3*(2*DI)], cw[e*4+0], s);
    g_xc[idx] = s / (1.f + expf(-s));
}

// ---------------- K6: selective scan + fused gating --------------------------
// Lanes: 16 per (b,e) channel, one per state n. y reduced by shfl only for
// output rows (l >= Tq); gate with silu(z) and D*xc applied inline -> g_yz.
__global__ void k_scan(const float* __restrict__ A_log, const float* __restrict__ Dp) {
    int gtid = blockIdx.x*blockDim.x + threadIdx.x;
    int grp = gtid >> 4;
    int n = gtid & 15;
    int b = grp >> 11;
    int e = grp & (DI-1);
    float Ac = -expf(A_log[e*DS + n]);
    float Dv = Dp[e];
    float h = 0.f;
    const float* dptr = g_delta + (size_t)b*Lseq*DI + e;
    const float* uptr = g_xc    + (size_t)b*Lseq*DI + e;
    const float* bc   = g_dbc   + (size_t)b*Lseq*96;
    const float* zptr = g_xz    + (size_t)b*Lseq*4096 + DI + e;
    float* yzp        = g_yz    + (size_t)b*Tq*DI + e;
    for (int l = 0; l < Lseq; l++) {
        float dv = dptr[(size_t)l*DI];
        float u  = uptr[(size_t)l*DI];
        float Bv = bc[l*96 + 64 + n];
        h = fmaf(__expf(dv*Ac), h, dv*Bv*u);
        if (l >= Tq) {
            float Cv = bc[l*96 + 80 + n];
            float p = h*Cv;
            p += __shfl_xor_sync(0xffffffffu, p, 1);
            p += __shfl_xor_sync(0xffffffffu, p, 2);
            p += __shfl_xor_sync(0xffffffffu, p, 4);
            p += __shfl_xor_sync(0xffffffffu, p, 8);
            if (n == 0) {
                float z = zptr[(size_t)l*4096];
                float gate = z / (1.f + expf(-z));
                yzp[(size_t)(l - Tq)*DI] = (p + u*Dv) * gate;
            }
        }
    }
}

// ---------------- K8: final residual + split-K reduce + layernorm ------------
__global__ void k_final(const float* __restrict__ ln_g, const float* __restrict__ ln_b,
                        float* __restrict__ out) {
    int lr = blockIdx.x;
    int b  = blockIdx.y;
    int t  = threadIdx.x;
    __shared__ float r1[8], r2[8];
    size_t srow = (size_t)(b*Lseq + Tq + lr)*DM;
    size_t mrow = (size_t)(b*Tq + lr)*DM;

    float loc[4];
    float s1 = 0.f, s2 = 0.f;
    #pragma unroll
    for (int i = 0; i < 4; i++) {
        int d = t + i*256;
        float v = g_seq[srow + d] + g_part[mrow + d] + g_part[(size_t)M2*DM + mrow + d];
        loc[i] = v; s1 += v; s2 += v*v;
    }
    int lane = t & 31, w = t >> 5;
    #pragma unroll
    for (int o = 16; o; o >>= 1) { s1 += __shfl_xor_sync(~0u, s1, o); s2 += __shfl_xor_sync(~0u, s2, o); }
    if (lane == 0) { r1[w] = s1; r2[w] = s2; }
    __syncthreads();
    if (t == 0) {
        float a = 0.f, c = 0.f;
        #pragma unroll
        for (int i = 0; i < 8; i++) { a += r1[i]; c += r2[i]; }
        r1[0] = a; r2[0] = c;
    }
    __syncthreads();
    float mu = r1[0] * (1.f/DM);
    float var = r2[0] * (1.f/DM) - mu*mu;
    float rstd = rsqrtf(var + 1e-5f);
    #pragma unroll
    for (int i = 0; i < 4; i++) {
        int d = t + i*256;
        out[mrow + d] = (loc[i] - mu) * rstd * ln_g[d] + ln_b[d];
    }
}

// ---------------- launch ------------------------------------------------------
extern "C" void kernel_launch(void* const* d_in, const int* in_sizes, int n_in,
                              void* d_out, int out_size) {
    const float* x_r       = (const float*)d_in[0];
    const int*   timesteps = (const int*)  d_in[1];
    const float* motion    = (const float*)d_in[2];
    const float* time_w1   = (const float*)d_in[3];
    const float* time_b1   = (const float*)d_in[4];
    const float* time_w2   = (const float*)d_in[5];
    const float* time_b2   = (const float*)d_in[6];
    const float* pos_emb   = (const float*)d_in[7];
    const float* ln_g      = (const float*)d_in[8];
    const float* ln_b      = (const float*)d_in[9];
    const float* in_proj_w = (const float*)d_in[10];
    const float* conv_w    = (const float*)d_in[11];
    const float* conv_b    = (const float*)d_in[12];
    const float* x_proj_w  = (const float*)d_in[13];
    const float* dt_proj_w = (const float*)d_in[14];
    const float* dt_proj_b = (const float*)d_in[15];
    const float* A_log     = (const float*)d_in[16];
    const float* Dp        = (const float*)d_in[17];
    const float* out_proj_w= (const float*)d_in[18];
    const float* rms_w     = (const float*)d_in[19];
    float* out = (float*)d_out;

    float *p_temb, *p_h, *p_embt, *p_xnorm, *p_xz, *p_xc, *p_dbc, *p_delta, *p_yz, *p_part;
    cudaGetSymbolAddress((void**)&p_temb,  g_temb);
    cudaGetSymbolAddress((void**)&p_h,     g_hmlp);
    cudaGetSymbolAddress((void**)&p_embt,  g_embt);
    cudaGetSymbolAddress((void**)&p_xnorm, g_xnorm);
    cudaGetSymbolAddress((void**)&p_xz,    g_xz);
    cudaGetSymbolAddress((void**)&p_xc,    g_xc);
    cudaGetSymbolAddress((void**)&p_dbc,   g_dbc);
    cudaGetSymbolAddress((void**)&p_delta, g_delta);
    cudaGetSymbolAddress((void**)&p_yz,    g_yz);
    cudaGetSymbolAddress((void**)&p_part,  g_part);

    // time embedding + MLP
    k_temb<<<Bsz, 512>>>(timesteps);
    k_mlp<<<dim3(2048/8, Bsz), 256>>>(p_temb, time_w1, time_b1, p_h, 1024, 2048, 1);
    k_mlp<<<dim3(1024/8, Bsz), 256>>>(p_h, time_w2, time_b2, p_embt, 2048, 1024, 0);

    // embed + LN -> seq, rms -> xnorm
    k_embed<<<dim3(Lseq, Bsz), 256>>>(x_r, motion, pos_emb, ln_g, ln_b, rms_w);

    // in_proj: xz = xnorm @ in_proj_w^T   [1568 x 4096], K=1024
    tgemm<0><<<dim3(4096/128, (MROWS+127)/128, 1), 256>>>(
        p_xnorm, in_proj_w, p_xz, MROWS, 4096, DM, DM, DM, nullptr);

    // depthwise conv + silu
    k_conv<<<(MROWS*DI + 255)/256, 256>>>(conv_w, conv_b);

    // x_proj: dbc = xc @ x_proj_w^T   [1568 x 96], K=2048, split-K=8
    tgemm<0><<<dim3(1, (MROWS+127)/128, 8), 256>>>(
        p_xc, x_proj_w, p_part, MROWS, 96, DI, DI, DI/8, nullptr);
    k_reduce<<<(MROWS*96 + 255)/256, 256>>>(p_part, p_dbc, MROWS*96, 8);

    // dt_proj + softplus: delta = softplus(dbc[:, :64] @ dt_proj_w^T + b)  [1568 x 2048], K=64
    tgemm<1><<<dim3(DI/128, (MROWS+127)/128, 1), 256>>>(
        p_dbc, dt_proj_w, p_delta, MROWS, DI, 96, DTR, DTR, dt_proj_b);

    // selective scan + fused gating -> g_yz
    k_scan<<<(Bsz*DI*DS)/256, 256>>>(A_log, Dp);

    // out_proj: partials = yz @ out_proj_w^T  [784 x 1024], K=2048, split-K=2
    tgemm<0><<<dim3(DM/128, (M2+127)/128, 2), 256>>>(
        p_yz, out_proj_w, p_part, M2, DM, DI, DI, DI/2, nullptr);

    // residual + split-K reduce + final LN
    k_final<<<dim3(Tq, Bsz), 256>>>(ln_g, ln_b, out);
}

// round 8
// speedup vs baseline: 3.0587x; 1.0444x over previous
#include <cuda_runtime.h>
#include <cuda_bf16.h>
#include <math.h>
#include <stdint.h>

#define Bsz   4
#define Tq    196
#define Lseq  392
#define DM    1024
#define DI    2048
#define DS    16
#define DTR   64
#define MROWS (Bsz*Lseq)   /* 1568 */
#define M2    (Bsz*Tq)     /* 784  */

typedef __nv_bfloat16 bf16;

// ---------------- scratch (static device globals; no allocation) -------------
__device__ float g_temb [Bsz*DM];
__device__ float g_hmlp [Bsz*2048];
__device__ float g_embt [Bsz*DM];
__device__ float g_seq  [MROWS*DM];
__device__ float g_xz   [(size_t)MROWS*2*DI];
__device__ float g_xc   [(size_t)MROWS*DI];
__device__ float g_dbc  [MROWS*96];
__device__ float g_delta[(size_t)MROWS*DI];
__device__ float g_part [(size_t)8*MROWS*96 > (size_t)2*M2*DM ? (size_t)8*MROWS*96 : (size_t)2*M2*DM];

// bf16 operand buffers
__device__ bf16 g_xnormh[(size_t)MROWS*DM];
__device__ bf16 g_xch   [(size_t)MROWS*DI];
__device__ bf16 g_dbch  [MROWS*96];
__device__ bf16 g_yzh   [(size_t)M2*DI];
__device__ bf16 g_wih   [(size_t)4096*DM];
__device__ bf16 g_wxh   [96*DI];
__device__ bf16 g_wdh   [DI*DTR];
__device__ bf16 g_woh   [(size_t)DM*DI];

// ---------------- helpers -----------------------------------------------------
__device__ __forceinline__ void mma16(float c[4], const uint32_t a[4], const uint32_t b[2]) {
    asm volatile(
        "mma.sync.aligned.m16n8k16.row.col.f32.bf16.bf16.f32 "
        "{%0,%1,%2,%3},{%4,%5,%6,%7},{%8,%9},{%0,%1,%2,%3};\n"
        : "+f"(c[0]), "+f"(c[1]), "+f"(c[2]), "+f"(c[3])
        : "r"(a[0]), "r"(a[1]), "r"(a[2]), "r"(a[3]), "r"(b[0]), "r"(b[1]));
}

#define CP16(dst, src) asm volatile("cp.async.cg.shared.global [%0], [%1], 16;\n" :: "r"(dst), "l"(src))
#define CP_COMMIT()    asm volatile("cp.async.commit_group;\n")
#define CP_WAIT1()     asm volatile("cp.async.wait_group 1;\n")
#define CP_WAIT0()     asm volatile("cp.async.wait_group 0;\n")

// ---------------- cvt fp32 -> bf16 -------------------------------------------
__global__ void k_cvt(const float* __restrict__ src, bf16* __restrict__ dst, int n) {
    int i = blockIdx.x * 256 + threadIdx.x;
    if (i < n) dst[i] = __float2bfloat16_rn(src[i]);
}

// ---------------- K1: timestep embedding -------------------------------------
__global__ void k_temb(const int* __restrict__ ts) {
    int b = blockIdx.x;
    int i = threadIdx.x;
    float t = (float)ts[b];
    float freq = expf(-logf(10000.0f) * (float)i / 512.0f);
    float arg = t * freq;
    g_temb[b*DM + i]       = cosf(arg);
    g_temb[b*DM + 512 + i] = sinf(arg);
}

// ---------------- K2/K3: tiny MLP via warp-per-output GEMV -------------------
__global__ void k_mlp(const float* __restrict__ X, const float* __restrict__ W,
                      const float* __restrict__ bias, float* __restrict__ Y,
                      int K, int N, int act) {
    int warp = (blockIdx.x * blockDim.x + threadIdx.x) >> 5;
    int lane = threadIdx.x & 31;
    int b = blockIdx.y;
    if (warp >= N) return;
    const float* x = X + b*K;
    const float* w = W + (size_t)warp*K;
    float s = 0.f;
    for (int k = lane; k < K; k += 32) s = fmaf(x[k], w[k], s);
    #pragma unroll
    for (int o = 16; o; o >>= 1) s += __shfl_xor_sync(0xffffffffu, s, o);
    if (lane == 0) {
        float v = s + bias[warp];
        if (act) v = v / (1.f + expf(-v));
        Y[b*N + warp] = v;
    }
}

// ---------------- K4: embed + LN -> seq, and RMS-norm -> xnorm(bf16) ---------
__global__ void k_embed(const float* __restrict__ x_r, const float* __restrict__ motion,
                        const float* __restrict__ pos,
                        const float* __restrict__ ln_g, const float* __restrict__ ln_b,
                        const float* __restrict__ rms_w) {
    int l = blockIdx.x;
    int b = blockIdx.y;
    int t = threadIdx.x;
    __shared__ float r1[8], r2[8];

    float loc[4];
    float s1 = 0.f, s2 = 0.f;
    #pragma unroll
    for (int i = 0; i < 4; i++) {
        int d = t + i*256;
        float v;
        if (l < Tq) {
            v = pos[l*DM + d] + motion[(size_t)(b*Tq + l)*DM + d];
        } else {
            int lr = l - Tq;
            v = pos[lr*DM + d] + x_r[(size_t)(b*Tq + lr)*DM + d] + g_embt[b*DM + d];
        }
        loc[i] = v; s1 += v; s2 += v*v;
    }
    int lane = t & 31, w = t >> 5;
    #pragma unroll
    for (int o = 16; o; o >>= 1) { s1 += __shfl_xor_sync(~0u, s1, o); s2 += __shfl_xor_sync(~0u, s2, o); }
    if (lane == 0) { r1[w] = s1; r2[w] = s2; }
    __syncthreads();
    if (t == 0) {
        float a = 0.f, c = 0.f;
        #pragma unroll
        for (int i = 0; i < 8; i++) { a += r1[i]; c += r2[i]; }
        r1[0] = a; r2[0] = c;
    }
    __syncthreads();
    float mu = r1[0] * (1.f/DM);
    float var = r2[0] * (1.f/DM) - mu*mu;
    float rstd = rsqrtf(var + 1e-5f);
    __syncthreads();

    float q = 0.f;
    size_t row = (size_t)(b*Lseq + l)*DM;
    #pragma unroll
    for (int i = 0; i < 4; i++) {
        int d = t + i*256;
        float ln = (loc[i] - mu) * rstd * ln_g[d] + ln_b[d];
        loc[i] = ln;
        q += ln*ln;
        g_seq[row + d] = ln;
    }
    #pragma unroll
    for (int o = 16; o; o >>= 1) q += __shfl_xor_sync(~0u, q, o);
    if (lane == 0) r1[w] = q;
    __syncthreads();
    if (t == 0) {
        float a = 0.f;
        #pragma unroll
        for (int i = 0; i < 8; i++) a += r1[i];
        r1[0] = a;
    }
    __syncthreads();
    float rrms = rsqrtf(r1[0] * (1.f/DM) + 1e-5f);
    #pragma unroll
    for (int i = 0; i < 4; i++) {
        int d = t + i*256;
        g_xnormh[row + d] = __float2bfloat16_rn(loc[i] * rrms * rms_w[d]);
    }
}

// ---------------- HGEMM: C[M,N] = A[M,K] . B[N,K]^T via bf16 m16n8k16 --------
// 128x128 block, 256 threads (8 warps: 2m x 4n, warp tile 64x32), BK=16.
// smem row stride 24 halves (48B): fragment-load banks all-distinct.
// Split-K: gridDim.z slices of klen each; slice z writes C + z*M*N.
// EPI==1: softplus(v + bias[n]) epilogue.
template<int EPI>
__global__ void __launch_bounds__(256)
hgemm(const bf16* __restrict__ A, const bf16* __restrict__ B,
      float* __restrict__ C, int M, int N, int lda, int ldb,
      int klen, const float* __restrict__ bias) {
    __shared__ bf16 As[2][128][24];
    __shared__ bf16 Bs[2][128][24];
    int tid = threadIdx.x;
    int bm0 = blockIdx.y * 128;
    int bn0 = blockIdx.x * 128;
    int kbeg = blockIdx.z * klen;
    C += (size_t)blockIdx.z * M * N;

    int warp = tid >> 5, lane = tid & 31;
    int wm = (warp & 1) * 64;
    int wn = (warp >> 1) * 32;
    int g = lane >> 2, r = lane & 3;

    float c[4][4][4];
    #pragma unroll
    for (int i = 0; i < 4; i++)
        #pragma unroll
        for (int j = 0; j < 4; j++)
            #pragma unroll
            for (int q = 0; q < 4; q++) c[i][j][q] = 0.f;

    int row_ld = tid >> 1;            // 0..127
    int ch_ld  = (tid & 1) * 8;       // 0 or 8 halves (16B chunks)

    auto prefetch = [&](int kt, int buf) {
        int k0 = kbeg + kt * 16 + ch_ld;
        int gm = min(bm0 + row_ld, M - 1);
        CP16((uint32_t)__cvta_generic_to_shared(&As[buf][row_ld][ch_ld]),
             &A[(size_t)gm * lda + k0]);
        int gn = min(bn0 + row_ld, N - 1);
        CP16((uint32_t)__cvta_generic_to_shared(&Bs[buf][row_ld][ch_ld]),
             &B[(size_t)gn * ldb + k0]);
    };

    int nk = klen / 16;
    prefetch(0, 0);
    CP_COMMIT();

    for (int kt = 0; kt < nk; kt++) {
        int buf = kt & 1;
        if (kt + 1 < nk) {
            prefetch(kt + 1, buf ^ 1);
            CP_COMMIT();
            CP_WAIT1();
        } else {
            CP_WAIT0();
        }
        __syncthreads();

        uint32_t bfr[4][2];
        #pragma unroll
        for (int j = 0; j < 4; j++) {
            bfr[j][0] = *(const uint32_t*)&Bs[buf][wn + j*8 + g][2*r];
            bfr[j][1] = *(const uint32_t*)&Bs[buf][wn + j*8 + g][2*r + 8];
        }
        #pragma unroll
        for (int i = 0; i < 4; i++) {
            uint32_t a[4];
            a[0] = *(const uint32_t*)&As[buf][wm + i*16 + g    ][2*r];
            a[1] = *(const uint32_t*)&As[buf][wm + i*16 + 8 + g][2*r];
            a[2] = *(const uint32_t*)&As[buf][wm + i*16 + g    ][2*r + 8];
            a[3] = *(const uint32_t*)&As[buf][wm + i*16 + 8 + g][2*r + 8];
            #pragma unroll
            for (int j = 0; j < 4; j++)
                mma16(c[i][j], a, bfr[j]);
        }
        __syncthreads();
    }

    // epilogue (float2 stores)
    #pragma unroll
    for (int i = 0; i < 4; i++) {
        #pragma unroll
        for (int half = 0; half < 2; half++) {
            int m = bm0 + wm + i*16 + g + half*8;
            if (m >= M) continue;
            #pragma unroll
            for (int j = 0; j < 4; j++) {
                int n = bn0 + wn + j*8 + 2*r;
                if (n >= N) continue;
                float v0 = c[i][j][half*2 + 0];
                float v1 = c[i][j][half*2 + 1];
                if (EPI == 1) {
                    v0 += bias[n];
                    v0 = (v0 > 20.f) ? v0 : log1pf(expf(v0));
                    v1 += bias[n + 1];
                    v1 = (v1 > 20.f) ? v1 : log1pf(expf(v1));
                }
                *(float2*)&C[(size_t)m*N + n] = make_float2(v0, v1);
            }
        }
    }
}

// ---------------- split-K reduce (x_proj) + bf16 copy ------------------------
__global__ void k_reduce(const float* __restrict__ part, float* __restrict__ out,
                         bf16* __restrict__ outh, int MN, int S) {
    int i = blockIdx.x * 256 + threadIdx.x;
    if (i >= MN) return;
    float s = 0.f;
    for (int z = 0; z < S; z++) s += part[(size_t)z*MN + i];
    out[i] = s;
    outh[i] = __float2bfloat16_rn(s);
}

// ---------------- K5: depthwise causal conv (w=4) + silu ---------------------
__global__ void k_conv(const float* __restrict__ cw, const float* __restrict__ cb) {
    int idx = blockIdx.x*256 + threadIdx.x;
    if (idx >= MROWS*DI) return;
    int e = idx & (DI-1);
    int bl = idx >> 11;
    int l = bl % Lseq;
    const float* base = g_xz + (size_t)bl*(2*DI) + e;
    float s = cb[e];
    s = fmaf(base[0], cw[e*4+3], s);
    if (l >= 1) s = fmaf(base[-(2*DI)],   cw[e*4+2], s);
    if (l >= 2) s = fmaf(base[-2*(2*DI)], cw[e*4+1], s);
    if (l >= 3) s = fmaf(base[-3*(2*DI)], cw[e*4+0], s);
    float v = s / (1.f + expf(-s));
    g_xc[idx] = v;
    g_xch[idx] = __float2bfloat16_rn(v);
}

// ---------------- K6: selective scan + fused gating --------------------------
__global__ void k_scan(const float* __restrict__ A_log, const float* __restrict__ Dp) {
    int gtid = blockIdx.x*blockDim.x + threadIdx.x;
    int grp = gtid >> 4;
    int n = gtid & 15;
    int b = grp >> 11;
    int e = grp & (DI-1);
    float Ac = -expf(A_log[e*DS + n]);
    float Dv = Dp[e];
    float h = 0.f;
    const float* dptr = g_delta + (size_t)b*Lseq*DI + e;
    const float* uptr = g_xc    + (size_t)b*Lseq*DI + e;
    const float* bc   = g_dbc   + (size_t)b*Lseq*96;
    const float* zptr = g_xz    + (size_t)b*Lseq*4096 + DI + e;
    bf16* yzp         = g_yzh   + (size_t)b*Tq*DI + e;
    for (int l = 0; l < Lseq; l++) {
        float dv = dptr[(size_t)l*DI];
        float u  = uptr[(size_t)l*DI];
        float Bv = bc[l*96 + 64 + n];
        h = fmaf(__expf(dv*Ac), h, dv*Bv*u);
        if (l >= Tq) {
            float Cv = bc[l*96 + 80 + n];
            float p = h*Cv;
            p += __shfl_xor_sync(0xffffffffu, p, 1);
            p += __shfl_xor_sync(0xffffffffu, p, 2);
            p += __shfl_xor_sync(0xffffffffu, p, 4);
            p += __shfl_xor_sync(0xffffffffu, p, 8);
            if (n == 0) {
                float z = zptr[(size_t)l*4096];
                float gate = z / (1.f + expf(-z));
                yzp[(size_t)(l - Tq)*DI] = __float2bfloat16_rn((p + u*Dv) * gate);
            }
        }
    }
}

// ---------------- K8: final residual + split-K reduce + layernorm ------------
__global__ void k_final(const float* __restrict__ ln_g, const float* __restrict__ ln_b,
                        float* __restrict__ out) {
    int lr = blockIdx.x;
    int b  = blockIdx.y;
    int t  = threadIdx.x;
    __shared__ float r1[8], r2[8];
    size_t srow = (size_t)(b*Lseq + Tq + lr)*DM;
    size_t mrow = (size_t)(b*Tq + lr)*DM;

    float loc[4];
    float s1 = 0.f, s2 = 0.f;
    #pragma unroll
    for (int i = 0; i < 4; i++) {
        int d = t + i*256;
        float v = g_seq[srow + d] + g_part[mrow + d] + g_part[(size_t)M2*DM + mrow + d];
        loc[i] = v; s1 += v; s2 += v*v;
    }
    int lane = t & 31, w = t >> 5;
    #pragma unroll
    for (int o = 16; o; o >>= 1) { s1 += __shfl_xor_sync(~0u, s1, o); s2 += __shfl_xor_sync(~0u, s2, o); }
    if (lane == 0) { r1[w] = s1; r2[w] = s2; }
    __syncthreads();
    if (t == 0) {
        float a = 0.f, c = 0.f;
        #pragma unroll
        for (int i = 0; i < 8; i++) { a += r1[i]; c += r2[i]; }
        r1[0] = a; r2[0] = c;
    }
    __syncthreads();
    float mu = r1[0] * (1.f/DM);
    float var = r2[0] * (1.f/DM) - mu*mu;
    float rstd = rsqrtf(var + 1e-5f);
    #pragma unroll
    for (int i = 0; i < 4; i++) {
        int d = t + i*256;
        out[mrow + d] = (loc[i] - mu) * rstd * ln_g[d] + ln_b[d];
    }
}

// ---------------- launch ------------------------------------------------------
extern "C" void kernel_launch(void* const* d_in, const int* in_sizes, int n_in,
                              void* d_out, int out_size) {
    const float* x_r       = (const float*)d_in[0];
    const int*   timesteps = (const int*)  d_in[1];
    const float* motion    = (const float*)d_in[2];
    const float* time_w1   = (const float*)d_in[3];
    const float* time_b1   = (const float*)d_in[4];
    const float* time_w2   = (const float*)d_in[5];
    const float* time_b2   = (const float*)d_in[6];
    const float* pos_emb   = (const float*)d_in[7];
    const float* ln_g      = (const float*)d_in[8];
    const float* ln_b      = (const float*)d_in[9];
    const float* in_proj_w = (const float*)d_in[10];
    const float* conv_w    = (const float*)d_in[11];
    const float* conv_b    = (const float*)d_in[12];
    const float* x_proj_w  = (const float*)d_in[13];
    const float* dt_proj_w = (const float*)d_in[14];
    const float* dt_proj_b = (const float*)d_in[15];
    const float* A_log     = (const float*)d_in[16];
    const float* Dp        = (const float*)d_in[17];
    const float* out_proj_w= (const float*)d_in[18];
    const float* rms_w     = (const float*)d_in[19];
    float* out = (float*)d_out;

    float *p_temb, *p_h, *p_embt, *p_xz, *p_xc, *p_dbc, *p_delta, *p_part;
    bf16 *p_xnormh, *p_xch, *p_dbch, *p_yzh, *p_wih, *p_wxh, *p_wdh, *p_woh;
    cudaGetSymbolAddress((void**)&p_temb,  g_temb);
    cudaGetSymbolAddress((void**)&p_h,     g_hmlp);
    cudaGetSymbolAddress((void**)&p_embt,  g_embt);
    cudaGetSymbolAddress((void**)&p_xz,    g_xz);
    cudaGetSymbolAddress((void**)&p_xc,    g_xc);
    cudaGetSymbolAddress((void**)&p_dbc,   g_dbc);
    cudaGetSymbolAddress((void**)&p_delta, g_delta);
    cudaGetSymbolAddress((void**)&p_part,  g_part);
    cudaGetSymbolAddress((void**)&p_xnormh,g_xnormh);
    cudaGetSymbolAddress((void**)&p_xch,   g_xch);
    cudaGetSymbolAddress((void**)&p_dbch,  g_dbch);
    cudaGetSymbolAddress((void**)&p_yzh,   g_yzh);
    cudaGetSymbolAddress((void**)&p_wih,   g_wih);
    cudaGetSymbolAddress((void**)&p_wxh,   g_wxh);
    cudaGetSymbolAddress((void**)&p_wdh,   g_wdh);
    cudaGetSymbolAddress((void**)&p_woh,   g_woh);

    // weight conversions (independent of activations)
    k_cvt<<<(4096*DM + 255)/256, 256>>>(in_proj_w,  p_wih, 4096*DM);
    k_cvt<<<(96*DI   + 255)/256, 256>>>(x_proj_w,   p_wxh, 96*DI);
    k_cvt<<<(DI*DTR  + 255)/256, 256>>>(dt_proj_w,  p_wdh, DI*DTR);
    k_cvt<<<(DM*DI   + 255)/256, 256>>>(out_proj_w, p_woh, DM*DI);

    // time embedding + MLP
    k_temb<<<Bsz, 512>>>(timesteps);
    k_mlp<<<dim3(2048/8, Bsz), 256>>>(p_temb, time_w1, time_b1, p_h, 1024, 2048, 1);
    k_mlp<<<dim3(1024/8, Bsz), 256>>>(p_h, time_w2, time_b2, p_embt, 2048, 1024, 0);

    // embed + LN -> seq, rms -> xnorm (bf16)
    k_embed<<<dim3(Lseq, Bsz), 256>>>(x_r, motion, pos_emb, ln_g, ln_b, rms_w);

    // in_proj: xz = xnorm @ in_proj_w^T   [1568 x 4096], K=1024
    hgemm<0><<<dim3(4096/128, (MROWS+127)/128, 1), 256>>>(
        p_xnormh, p_wih, p_xz, MROWS, 4096, DM, DM, DM, nullptr);

    // depthwise conv + silu (fp32 + bf16 outputs)
    k_conv<<<(MROWS*DI + 255)/256, 256>>>(conv_w, conv_b);

    // x_proj: dbc = xc @ x_proj_w^T   [1568 x 96], K=2048, split-K=8
    hgemm<0><<<dim3(1, (MROWS+127)/128, 8), 256>>>(
        p_xch, p_wxh, p_part, MROWS, 96, DI, DI, DI/8, nullptr);
    k_reduce<<<(MROWS*96 + 255)/256, 256>>>(p_part, p_dbc, p_dbch, MROWS*96, 8);

    // dt_proj + softplus: delta = softplus(dbc[:, :64] @ dt_proj_w^T + b)  [1568 x 2048], K=64
    hgemm<1><<<dim3(DI/128, (MROWS+127)/128, 1), 256>>>(
        p_dbch, p_wdh, p_delta, MROWS, DI, 96, DTR, DTR, dt_proj_b);

    // selective scan + fused gating -> g_yzh (bf16)
    k_scan<<<(Bsz*DI*DS)/256, 256>>>(A_log, Dp);

    // out_proj: partials = yz @ out_proj_w^T  [784 x 1024], K=2048, split-K=2
    hgemm<0><<<dim3(DM/128, (M2+127)/128, 2), 256>>>(
        p_yzh, p_woh, p_part, M2, DM, DI, DI, DI/2, nullptr);

    // residual + split-K reduce + final LN
    k_final<<<dim3(Tq, Bsz), 256>>>(ln_g, ln_b, out);
}